// round 3
// baseline (speedup 1.0000x reference)
#include <cuda_runtime.h>

#define BB 8
#define CC 192
#define CQ 32
#define NN 16384
#define TILE 64
#define NT (NN / TILE)   // 256 tiles per batch

// ---------------- scratch (static device globals; no allocations) ----------------
__device__ float g_Qn[(size_t)BB * NN * CQ];            // [b][n][r]   16 MB
__device__ float g_Kn[(size_t)BB * CQ * NN];            // [b][r][n]   16 MB
__device__ float g_MatPart[(size_t)BB * NT * CQ * CC];  // per-tile partial matrix, 50 MB
__device__ float g_VsumPart[(size_t)BB * NT * CC];      // per-tile partial value_sum
__device__ float g_Mat[BB * CQ * CC];
__device__ float g_Vsum[BB * CC];
__device__ float g_KsumE[BB * CQ];                      // Ksum + EPS

// ---------------- kernel 1: Q,K projection + per-column L2 norm ----------------
__global__ __launch_bounds__(256) void qk_kernel(
    const float* __restrict__ x1, const float* __restrict__ Wq,
    const float* __restrict__ bq, const float* __restrict__ Wk,
    const float* __restrict__ bk)
{
    extern __shared__ float smem[];
    float* sX = smem;               // [CC][64]
    float* sW = smem + CC * TILE;   // [64][CC]  rows 0-31 Wq, 32-63 Wk
    const int tid = threadIdx.x;
    const int b = blockIdx.y;
    const int n0 = blockIdx.x * TILE;

    const float* xb = x1 + (size_t)b * CC * NN + n0;
    for (int i = tid; i < CC * TILE; i += 256) {
        int c = i >> 6, j = i & 63;
        sX[i] = xb[(size_t)c * NN + j];
    }
    for (int i = tid; i < 64 * CC; i += 256) {
        int o = i / CC, c = i - o * CC;
        sW[i] = (o < CQ) ? Wq[o * CC + c] : Wk[(o - CQ) * CC + c];
    }
    __syncthreads();

    const int ty = tid >> 4, tx = tid & 15;   // 16x16 threads, 4x4 microtile
    float acc[4][4];
    #pragma unroll
    for (int a = 0; a < 4; a++)
        #pragma unroll
        for (int e = 0; e < 4; e++) acc[a][e] = 0.f;

    const float4* sX4 = (const float4*)sX;
    #pragma unroll 4
    for (int kc = 0; kc < CC; kc++) {
        float4 xv = sX4[kc * 16 + tx];
        #pragma unroll
        for (int oo = 0; oo < 4; oo++) {
            float w = sW[(ty * 4 + oo) * CC + kc];
            acc[oo][0] += w * xv.x;
            acc[oo][1] += w * xv.y;
            acc[oo][2] += w * xv.z;
            acc[oo][3] += w * xv.w;
        }
    }
    #pragma unroll
    for (int oo = 0; oo < 4; oo++) {
        int o = ty * 4 + oo;
        float bias = (o < CQ) ? __ldg(&bq[o]) : __ldg(&bk[o - CQ]);
        #pragma unroll
        for (int jj = 0; jj < 4; jj++) acc[oo][jj] += bias;
    }
    __syncthreads();   // done reading sX/sW

    float* sQK  = smem;               // [64][68]  (reuses sX region)
    float* sNrm = smem + CC * TILE;   // [128]     (reuses sW region)
    #pragma unroll
    for (int oo = 0; oo < 4; oo++)
        #pragma unroll
        for (int jj = 0; jj < 4; jj++)
            sQK[(ty * 4 + oo) * 68 + tx * 4 + jj] = acc[oo][jj];
    __syncthreads();

    if (tid < 128) {              // 64 q-norms, 64 k-norms
        int j = tid & 63, h = tid >> 6;
        float s = 0.f;
        #pragma unroll
        for (int r = 0; r < CQ; r++) {
            float v = sQK[(h * CQ + r) * 68 + j];
            s += v * v;
        }
        sNrm[tid] = rsqrtf(s);
    }
    __syncthreads();

    float* gq = g_Qn + (size_t)(b * NN + n0) * CQ;
    for (int i = tid; i < CQ * TILE; i += 256) {   // coalesced [n][r] writes
        int j = i >> 5, r = i & 31;
        gq[i] = sQK[r * 68 + j] * sNrm[j];
    }
    for (int i = tid; i < CQ * TILE; i += 256) {   // coalesced [r][n] writes
        int r = i >> 6, j = i & 63;
        g_Kn[(size_t)(b * CQ + r) * NN + n0 + j] = sQK[(CQ + r) * 68 + j] * sNrm[64 + j];
    }
}

// ---------------- kernel 2: V projection (fused, not materialized) + matrix/value_sum partials ----------------
__global__ __launch_bounds__(256) void vmat_kernel(
    const float* __restrict__ x, const float* __restrict__ Wv,
    const float* __restrict__ bv)
{
    extern __shared__ float smem[];
    float* sX  = smem;                  // [CC][64]   (region sized CC*66 for sV reuse)
    float* sWv = smem + CC * 66;        // [CC][33]   (32-wide chunk of Wv, padded)
    float* sKn = sWv + CC * 33;         // [CQ][64]
    const int tid = threadIdx.x;
    const int b = blockIdx.y;
    const int tile = blockIdx.x;
    const int n0 = tile * TILE;

    const float* xb = x + (size_t)b * CC * NN + n0;
    for (int i = tid; i < CC * TILE; i += 256) {
        int c = i >> 6, j = i & 63;
        sX[i] = xb[(size_t)c * NN + j];
    }
    for (int i = tid; i < CQ * TILE; i += 256) {
        int r = i >> 6, j = i & 63;
        sKn[i] = g_Kn[(size_t)(b * CQ + r) * NN + n0 + j];
    }

    const int ty = tid >> 4, tx = tid & 15;   // each thread: 12 out-rows x 4 cols
    float acc[12][4];
    #pragma unroll
    for (int a = 0; a < 12; a++)
        #pragma unroll
        for (int e = 0; e < 4; e++) acc[a][e] = 0.f;

    const float4* sX4 = (const float4*)sX;
    for (int c0 = 0; c0 < CC; c0 += 32) {
        __syncthreads();   // (also covers the initial sX/sKn loads at c0==0)
        for (int i = tid; i < CC * 32; i += 256) {
            int o = i >> 5, kcl = i & 31;
            sWv[o * 33 + kcl] = Wv[o * CC + c0 + kcl];
        }
        __syncthreads();
        #pragma unroll 2
        for (int kcl = 0; kcl < 32; kcl++) {
            float4 xv = sX4[(c0 + kcl) * 16 + tx];
            #pragma unroll
            for (int oo = 0; oo < 12; oo++) {
                float w = sWv[(ty * 12 + oo) * 33 + kcl];
                acc[oo][0] += w * xv.x;
                acc[oo][1] += w * xv.y;
                acc[oo][2] += w * xv.z;
                acc[oo][3] += w * xv.w;
            }
        }
    }
    __syncthreads();   // done reading sX

    float* sV = smem;   // [CC][66]  (reuses sX region)
    #pragma unroll
    for (int oo = 0; oo < 12; oo++) {
        int o = ty * 12 + oo;
        float bias = __ldg(&bv[o]);
        #pragma unroll
        for (int jj = 0; jj < 4; jj++)
            sV[o * 66 + tx * 4 + jj] = acc[oo][jj] + bias;
    }
    __syncthreads();

    // matrix partial: mat[m][c] += sum_j Kn[m][j] * V[c][j]   (float2 over j)
    const int m  = tid >> 3;   // 0..31
    const int t8 = tid & 7;    // c = q*8 + t8
    float acc2[24];
    #pragma unroll
    for (int q = 0; q < 24; q++) acc2[q] = 0.f;

    const float2* sV2 = (const float2*)sV;   // row stride 33 float2
    const float2* sK2 = (const float2*)sKn;  // row stride 32 float2
    #pragma unroll 4
    for (int j2 = 0; j2 < 32; j2++) {
        float2 kv = sK2[m * 32 + j2];
        #pragma unroll
        for (int q = 0; q < 24; q++) {
            float2 vv = sV2[(q * 8 + t8) * 33 + j2];
            acc2[q] += kv.x * vv.x + kv.y * vv.y;
        }
    }
    float* matp = g_MatPart + (size_t)(b * NT + tile) * (CQ * CC);
    #pragma unroll
    for (int q = 0; q < 24; q++)
        matp[m * CC + q * 8 + t8] = acc2[q];

    if (tid < CC) {   // value_sum partial
        float s = 0.f;
        const float2* row = (const float2*)(sV + tid * 66);
        #pragma unroll 8
        for (int j2 = 0; j2 < 32; j2++) s += row[j2].x + row[j2].y;
        g_VsumPart[(size_t)(b * NT + tile) * CC + tid] = s;
    }
}

// ---------------- deterministic reductions ----------------
__global__ __launch_bounds__(256) void ksum_kernel()
{
    const int r = blockIdx.x, b = blockIdx.y;
    const float* p = g_Kn + (size_t)(b * CQ + r) * NN;
    float s = 0.f;
    for (int i = threadIdx.x; i < NN; i += 256) s += p[i];
    __shared__ float red[256];
    red[threadIdx.x] = s;
    __syncthreads();
    for (int st = 128; st > 0; st >>= 1) {
        if (threadIdx.x < st) red[threadIdx.x] += red[threadIdx.x + st];
        __syncthreads();
    }
    if (threadIdx.x == 0) g_KsumE[b * CQ + r] = red[0] + 1e-6f;
}

__global__ __launch_bounds__(256) void matred_kernel()
{
    const int b = blockIdx.y;
    const int i = blockIdx.x * 256 + threadIdx.x;   // < CQ*CC = 6144
    const float* p = g_MatPart + (size_t)b * NT * (CQ * CC) + i;
    float s = 0.f;
    for (int t = 0; t < NT; t++) s += p[(size_t)t * (CQ * CC)];
    g_Mat[b * CQ * CC + i] = s;
}

__global__ __launch_bounds__(192) void vsumred_kernel()
{
    const int b = blockIdx.x;
    const int c = threadIdx.x;   // < 192
    const float* p = g_VsumPart + (size_t)b * NT * CC + c;
    float s = 0.f;
    for (int t = 0; t < NT; t++) s += p[(size_t)t * CC];
    g_Vsum[b * CC + c] = s;
}

// ---------------- kernel 6: epilogue ----------------
__global__ __launch_bounds__(256) void final_kernel(
    const float* __restrict__ gamma, float* __restrict__ out)
{
    __shared__ float sQn[TILE * 33];   // [j][r] padded
    __shared__ float sMat[CQ * CC];
    __shared__ float sVs[CC];
    __shared__ float sKs[CQ];
    __shared__ float sTail[TILE];
    const int tid = threadIdx.x;
    const int b = blockIdx.y;
    const int n0 = blockIdx.x * TILE;

    const float* gq = g_Qn + (size_t)(b * NN + n0) * CQ;
    for (int i = tid; i < TILE * CQ; i += 256) {
        int j = i >> 5, r = i & 31;
        sQn[j * 33 + r] = gq[i];
    }
    for (int i = tid; i < CQ * CC; i += 256) sMat[i] = g_Mat[b * CQ * CC + i];
    if (tid < CC) sVs[tid] = g_Vsum[b * CC + tid];
    if (tid < CQ) sKs[tid] = g_KsumE[b * CQ + tid];
    __syncthreads();

    if (tid < TILE) {
        float s = 0.f;
        #pragma unroll
        for (int r = 0; r < CQ; r++) s += sQn[tid * 33 + r] * sKs[r];
        sTail[tid] = 1.0f / ((float)NN + s);
    }
    __syncthreads();

    const float g = __ldg(gamma);
    const int j = tid & 63, cy = tid >> 6;   // warp: 32 consecutive j, same cy
    float q[CQ];
    #pragma unroll
    for (int r = 0; r < CQ; r++) q[r] = sQn[j * 33 + r];
    const float tl = sTail[j] * g;

    float* ob = out + (size_t)b * CC * NN + n0 + j;
    for (int c = cy; c < CC; c += 4) {
        float a = sVs[c];
        #pragma unroll
        for (int r = 0; r < CQ; r++) a += q[r] * sMat[r * CC + c];   // broadcast reads
        ob[(size_t)c * NN] = a * tl;                                  // coalesced over j
    }
}

// ---------------- launch ----------------
extern "C" void kernel_launch(void* const* d_in, const int* in_sizes, int n_in,
                              void* d_out, int out_size)
{
    const float* x  = (const float*)d_in[0];
    const float* x1 = (const float*)d_in[1];
    const float* Wq = (const float*)d_in[2];
    const float* bq = (const float*)d_in[3];
    const float* Wk = (const float*)d_in[4];
    const float* bk = (const float*)d_in[5];
    const float* Wv = (const float*)d_in[6];
    const float* bv = (const float*)d_in[7];
    const float* gm = (const float*)d_in[8];
    float* out = (float*)d_out;

    const int smemQK = (CC * TILE + 64 * CC) * 4;              // 96 KB
    const int smemV  = (CC * 66 + CC * 33 + CQ * TILE) * 4;    // ~82 KB
    cudaFuncSetAttribute(qk_kernel,  cudaFuncAttributeMaxDynamicSharedMemorySize, smemQK);
    cudaFuncSetAttribute(vmat_kernel, cudaFuncAttributeMaxDynamicSharedMemorySize, smemV);

    dim3 grid(NT, BB);
    qk_kernel<<<grid, 256, smemQK>>>(x1, Wq, bq, Wk, bk);
    vmat_kernel<<<grid, 256, smemV>>>(x, Wv, bv);
    ksum_kernel<<<dim3(CQ, BB), 256>>>();
    matred_kernel<<<dim3((CQ * CC) / 256, BB), 256>>>();
    vsumred_kernel<<<BB, 192>>>();
    final_kernel<<<grid, 256>>>(gm, out);
}